// round 14
// baseline (speedup 1.0000x reference)
#include <cuda_runtime.h>
#include <cstdint>

// Problem constants
#define NV 128   // vocab
#define NE 64    // embed
#define NH 128   // hidden
#define NC 12    // classes
#define NB 2048  // batch
#define NT 256   // timesteps
#define NBLK 64  // blocks (both kernels)
#define VPB 2    // vocab rows per prep block
#define BPB 32   // batches per main block (2 per warp)
#define NTHR 512
#define THRESH 0.9995f
#define FULL 0xFFFFFFFFu

// 0.8^n constants
#define P8_1 0.8f
#define P8_2 0.64f
#define P8_4 0.4096f
#define P8_8 0.16777216f
#define P8_16 0.028147497671065608f
#define P8_32 0.0007922816251426434f

// Scratch (device globals: no allocation allowed; zero-initialized once)
__device__ float g_Q[NV * NH];  // 0.2*((emb[v]@W_in^T+b_in)@W_lif0^T+b_lif0)
__device__ float g_M[NV];       // row max of Q
__device__ unsigned g_gmax;     // order-encoded max(Q,0); idempotent

// ---------------------------------------------------------------------------
// Kernel 1: prep. 64 blocks x 512 threads, 2 vocab rows per block.
// Publishes g_Q, g_M, g_gmax. Visibility to kernel 2 via the graph edge.
// ---------------------------------------------------------------------------
__global__ __launch_bounds__(NTHR, 1) void snn_prep_kernel(
    const float* __restrict__ emb, const float* __restrict__ W_in,
    const float* __restrict__ b_in, const float* __restrict__ W_lif,
    const float* __restrict__ b_lif) {
    __shared__ __align__(16) float psh[VPB * NH];
    __shared__ float wmaxa[16], wmaxb[16];

    const int tid = threadIdx.x;
    const int lane = tid & 31;
    const int warp = tid >> 5;
    const int v0i = blockIdx.x * VPB;
    const int h4 = lane * 4;

    // ---- prefetch (one MLP window) ----
    const float ea0 = __ldg(emb + v0i * NE + lane);
    const float ea1 = __ldg(emb + v0i * NE + 32 + lane);
    const float eb0 = __ldg(emb + (v0i + 1) * NE + lane);
    const float eb1 = __ldg(emb + (v0i + 1) * NE + 32 + lane);
    float wi0[8], wi1[8];
    float4 wv[8];
#pragma unroll
    for (int r = 0; r < 8; r++) {
        const int h = warp * 8 + r;
        wi0[r] = __ldg(W_in + h * NE + lane);
        wi1[r] = __ldg(W_in + h * NE + 32 + lane);
        wv[r] = __ldg((const float4*)(W_lif + h * NH + h4));
    }
    const float bin = (lane < 8) ? __ldg(b_in + warp * 8 + lane) : 0.f;
    const float bl0 = (lane < 8) ? __ldg(b_lif + warp * 8 + lane) : 0.f;

    // ---- P[v,h] = emb[v]@W_in[h,:] + b_in[h], v in {a,b} ----
    {
        float pa[8], pb[8];
#pragma unroll
        for (int r = 0; r < 8; r++) {
            pa[r] = fmaf(wi0[r], ea0, wi1[r] * ea1);
            pb[r] = fmaf(wi0[r], eb0, wi1[r] * eb1);
        }
#pragma unroll
        for (int r = 0; r < 8; r++) {
#pragma unroll
            for (int d = 16; d > 0; d >>= 1) {
                pa[r] += __shfl_xor_sync(FULL, pa[r], d);
                pb[r] += __shfl_xor_sync(FULL, pb[r], d);
            }
            if (lane == r) {
                psh[warp * 8 + r] = pa[r] + bin;
                psh[NH + warp * 8 + r] = pb[r] + bin;
            }
        }
    }
    __syncthreads();

    // ---- Q[v,h] = 0.2*(P[v] . W_lif0[h,:] + b_lif0[h]) ----
    {
        const float4 pva = *(const float4*)(psh + h4);
        const float4 pvb = *(const float4*)(psh + NH + h4);
        float qa[8], qb[8];
#pragma unroll
        for (int r = 0; r < 8; r++) {
            qa[r] = fmaf(wv[r].x, pva.x,
                         fmaf(wv[r].y, pva.y,
                              fmaf(wv[r].z, pva.z, wv[r].w * pva.w)));
            qb[r] = fmaf(wv[r].x, pvb.x,
                         fmaf(wv[r].y, pvb.y,
                              fmaf(wv[r].z, pvb.z, wv[r].w * pvb.w)));
        }
        float qav = -1e30f, qbv = -1e30f;
#pragma unroll
        for (int r = 0; r < 8; r++) {
#pragma unroll
            for (int d = 16; d > 0; d >>= 1) {
                qa[r] += __shfl_xor_sync(FULL, qa[r], d);
                qb[r] += __shfl_xor_sync(FULL, qb[r], d);
            }
            if (lane == r) {
                const float qqa = 0.2f * (qa[r] + bl0);
                const float qqb = 0.2f * (qb[r] + bl0);
                g_Q[v0i * NH + warp * 8 + r] = qqa;        // fire-and-forget
                g_Q[(v0i + 1) * NH + warp * 8 + r] = qqb;
                qav = qqa;
                qbv = qqb;
            }
        }
#pragma unroll
        for (int d = 16; d > 0; d >>= 1) {
            qav = fmaxf(qav, __shfl_xor_sync(FULL, qav, d));
            qbv = fmaxf(qbv, __shfl_xor_sync(FULL, qbv, d));
        }
        if (lane == 0) {
            wmaxa[warp] = qav;
            wmaxb[warp] = qbv;
        }
    }
    __syncthreads();
    if (tid == 0) {
        float ma = wmaxa[0], mb = wmaxb[0];
#pragma unroll
        for (int w = 1; w < 16; w++) {
            ma = fmaxf(ma, wmaxa[w]);
            mb = fmaxf(mb, wmaxb[w]);
        }
        g_M[v0i] = ma;
        g_M[v0i + 1] = mb;
        // clamped-at-0, order-encoded contribution (nonneg floats preserve
        // order in uint once the MSB is set). Idempotent across replays.
        const float g = fmaxf(fmaxf(ma, mb), 0.f);
        atomicMax(&g_gmax, __float_as_uint(g) | 0x80000000u);
    }
}

// ---------------------------------------------------------------------------
// Kernel 2: decide + emit. 64 blocks x 512 threads, 2 batches per warp.
// Fast path: no smem, no syncthreads — one LDG and a store.
// ---------------------------------------------------------------------------
__global__ __launch_bounds__(NTHR, 1) void snn_main_kernel(
    const int* __restrict__ ids, const float* __restrict__ W_lif,
    const float* __restrict__ b_lif, const float* __restrict__ W_cls,
    const float* __restrict__ b_cls, float* __restrict__ out) {
    __shared__ __align__(16) float Ms[NV];
    __shared__ int idsh[16 * NT];

    const int tid = threadIdx.x;
    const int lane = tid & 31;
    const int warp = tid >> 5;
    const int b0 = blockIdx.x * BPB;
    const int h4 = lane * 4;

    // fast-path operands (issued together)
    const unsigned genc = __ldg(&g_gmax);
    float b1[4];
#pragma unroll
    for (int j = 0; j < 4; j++) b1[j] = __ldg(b_lif + NH + h4 + j);
    const float bc = (lane < NC) ? __ldg(b_cls + lane) : 0.f;

    const float gmax = __uint_as_float(genc & 0x7FFFFFFFu);
    const bool bias_safe = __all_sync(
        FULL, (0.2f * b1[0] < 0.19999f) && (0.2f * b1[1] < 0.19999f) &&
                  (0.2f * b1[2] < 0.19999f) && (0.2f * b1[3] < 0.19999f));

    // ============ tier 0: global no-spike certificate ============
    // u_t <= sum_j 0.8^j max_v M[v] <= 5*max(M*,0) for every batch/step.
    if (bias_safe && 5.0f * gmax < THRESH) {
        if (lane < NC) {
            out[(b0 + warp) * NC + lane] = bc;
            out[(b0 + 16 + warp) * NC + lane] = bc;
        }
        return;  // globally uniform decision
    }

    // ============ tier 1+: scan / exact replay ============
    if (tid < NV / 4) ((float4*)Ms)[tid] = ((const float4*)g_M)[tid];
    __syncthreads();

    const float* W1 = W_lif + NH * NH;

    for (int bb = 0; bb < 2; bb++) {
        const int b = b0 + bb * 16 + warp;
        int myid[8];
#pragma unroll
        for (int c = 0; c < 8; c++)
            myid[c] = __ldg(ids + b * NT + c * 32 + lane);

        // phase 1: carry-independent chunk scans
        float mxs[8], s31[8];
#pragma unroll
        for (int c = 0; c < 8; c++) {
            float s = Ms[myid[c]];
            float o;
            o = __shfl_up_sync(FULL, s, 1);
            if (lane >= 1) s = fmaf(P8_1, o, s);
            o = __shfl_up_sync(FULL, s, 2);
            if (lane >= 2) s = fmaf(P8_2, o, s);
            o = __shfl_up_sync(FULL, s, 4);
            if (lane >= 4) s = fmaf(P8_4, o, s);
            o = __shfl_up_sync(FULL, s, 8);
            if (lane >= 8) s = fmaf(P8_8, o, s);
            o = __shfl_up_sync(FULL, s, 16);
            if (lane >= 16) s = fmaf(P8_16, o, s);
            float m = s;
#pragma unroll
            for (int d = 16; d > 0; d >>= 1)
                m = fmaxf(m, __shfl_xor_sync(FULL, m, d));
            mxs[c] = m;
            s31[c] = __shfl_sync(FULL, s, 31);
        }

        // phase 2: serial carry + (rare) exact replay
        float v0[4] = {0.f, 0.f, 0.f, 0.f};
        float v1[4] = {0.f, 0.f, 0.f, 0.f};
        float acc[4] = {0.f, 0.f, 0.f, 0.f};
        int tck = 0;
        float u = 0.f;
        bool staged = false;

        for (int c = 0; c < 8; c++) {
            const float bnd = fmaf(0.8f, fmaxf(u, 0.f), mxs[c]);
            if (!bias_safe || bnd >= THRESH) {
                if (!staged) {
#pragma unroll
                    for (int cc = 0; cc < 8; cc++)
                        idsh[warp * NT + cc * 32 + lane] = myid[cc];
                    __syncwarp();
                    staged = true;
                }
                const int tend = (c + 1) * 32;
                for (int t = tck; t < tend; t++) {
                    const int id = idsh[warp * NT + t];
                    const float4 q =
                        __ldg((const float4*)(g_Q + id * NH + h4));
                    float n0 = fmaf(0.8f, v0[0], q.x);
                    float n1 = fmaf(0.8f, v0[1], q.y);
                    float n2 = fmaf(0.8f, v0[2], q.z);
                    float n3 = fmaf(0.8f, v0[3], q.w);
                    unsigned bm[4];
                    bm[0] = __ballot_sync(FULL, n0 >= 1.0f);
                    bm[1] = __ballot_sync(FULL, n1 >= 1.0f);
                    bm[2] = __ballot_sync(FULL, n2 >= 1.0f);
                    bm[3] = __ballot_sync(FULL, n3 >= 1.0f);
                    v0[0] = (n0 >= 1.0f) ? 0.f : n0;
                    v0[1] = (n1 >= 1.0f) ? 0.f : n1;
                    v0[2] = (n2 >= 1.0f) ? 0.f : n2;
                    v0[3] = (n3 >= 1.0f) ? 0.f : n3;

                    float cur[4] = {0.f, 0.f, 0.f, 0.f};
#pragma unroll
                    for (int w = 0; w < 4; w++) {
                        unsigned mm = bm[w];
                        while (mm) {
                            const int l = __ffs(mm) - 1;
                            mm &= mm - 1;
                            const float* col = W1 + (l * 4 + w);
                            cur[0] += __ldg(col + (h4 + 0) * NH);
                            cur[1] += __ldg(col + (h4 + 1) * NH);
                            cur[2] += __ldg(col + (h4 + 2) * NH);
                            cur[3] += __ldg(col + (h4 + 3) * NH);
                        }
                    }
#pragma unroll
                    for (int j = 0; j < 4; j++) {
                        const float cc2 = cur[j] + b1[j];
                        const float vv = 0.8f * v1[j] + 0.2f * cc2;
                        const bool s = (vv >= 1.0f);
                        acc[j] += s ? 1.f : 0.f;
                        v1[j] = s ? 0.f : vv;
                    }
                }
                tck = tend;
                float w = fmaxf(fmaxf(v0[0], v0[1]), fmaxf(v0[2], v0[3]));
#pragma unroll
                for (int d = 16; d > 0; d >>= 1)
                    w = fmaxf(w, __shfl_xor_sync(FULL, w, d));
                u = w;
            } else {
                u = fmaf(P8_32, u, s31[c]);
            }
        }

        // epilogue for this batch
        if (tck == 0) {
            if (lane < NC) out[b * NC + lane] = bc;
        } else {
            const float invT = 1.0f / (float)NT;
#pragma unroll
            for (int cc = 0; cc < NC; cc++) {
                const float* wc = W_cls + cc * NH + h4;
                float p = acc[0] * __ldg(wc + 0) + acc[1] * __ldg(wc + 1) +
                          acc[2] * __ldg(wc + 2) + acc[3] * __ldg(wc + 3);
#pragma unroll
                for (int d = 16; d > 0; d >>= 1)
                    p += __shfl_xor_sync(FULL, p, d);
                if (lane == 0) out[b * NC + cc] = p * invT + b_cls[cc];
            }
        }
    }
}

// ---------------------------------------------------------------------------
// Host launcher (graph-capturable: two kernel launches, stream-ordered)
// Input order: ids, emb, W_in, b_in, W_lif, b_lif, W_rec(unused), W_cls, b_cls
// ---------------------------------------------------------------------------
extern "C" void kernel_launch(void* const* d_in, const int* in_sizes, int n_in,
                              void* d_out, int out_size) {
    const int* ids = (const int*)d_in[0];
    const float* emb = (const float*)d_in[1];
    const float* W_in = (const float*)d_in[2];
    const float* b_in = (const float*)d_in[3];
    const float* W_lif = (const float*)d_in[4];
    const float* b_lif = (const float*)d_in[5];
    const float* W_cls = (const float*)d_in[7];
    const float* b_cls = (const float*)d_in[8];
    float* out = (float*)d_out;

    snn_prep_kernel<<<NBLK, NTHR>>>(emb, W_in, b_in, W_lif, b_lif);
    snn_main_kernel<<<NBLK, NTHR>>>(ids, W_lif, b_lif, W_cls, b_cls, out);
}

// round 15
// speedup vs baseline: 1.0552x; 1.0552x over previous
#include <cuda_runtime.h>
#include <cstdint>

// Problem constants
#define NV 128   // vocab
#define NE 64    // embed
#define NH 128   // hidden
#define NC 12    // classes
#define NB 2048  // batch
#define NT 256   // timesteps
#define NBLK 64  // blocks
#define VPB 2    // vocab rows per block
#define BPB 32   // batches per block (2 per warp)
#define NTHR 512
#define THRESH 0.9995f
#define FULL 0xFFFFFFFFu

// 0.8^n constants
#define P8_1 0.8f
#define P8_2 0.64f
#define P8_4 0.4096f
#define P8_8 0.16777216f
#define P8_16 0.028147497671065608f
#define P8_32 0.0007922816251426434f

// Scratch (device globals: no allocation allowed; zero-initialized once)
__device__ float g_Q[NV * NH];  // written only on the (rare) tier-1+ path
__device__ float g_M[NV];       // written only on tier-1+
__device__ unsigned g_gmax;     // order-encoded max(Q,0); idempotent
__device__ unsigned g_cnt1;     // epoch counter #1
__device__ unsigned g_cnt2;     // epoch counter #2 (tier-1+ only)

// Cheap L2-scope load for barrier polling / certificate decode.
__device__ __forceinline__ unsigned ld_cg(const unsigned* p) {
    unsigned v;
    asm volatile("ld.global.cg.u32 %0, [%1];" : "=r"(v) : "l"(p));
    return v;
}

// Modular epoch barrier: REDG arrive + cg-poll until count % NBLK == 0.
// tid0 does release fence before arrive; acquire fence after; __syncthreads
// extends the ordering to the block (cooperative-groups idiom).
__device__ __forceinline__ void epoch_barrier(unsigned* cnt, int tid) {
    if (tid == 0) {
        __threadfence();     // release this block's prior global writes
        atomicAdd(cnt, 1u);  // return unused -> REDG
        while ((ld_cg(cnt) & (NBLK - 1)) != 0u) {
        }
        __threadfence();     // acquire
    }
    __syncthreads();
}

__global__ __launch_bounds__(NTHR, 1) void snn_fused_kernel(
    const int* __restrict__ ids, const float* __restrict__ emb,
    const float* __restrict__ W_in, const float* __restrict__ b_in,
    const float* __restrict__ W_lif, const float* __restrict__ b_lif,
    const float* __restrict__ W_cls, const float* __restrict__ b_cls,
    float* __restrict__ out) {
    __shared__ __align__(16) float psh[VPB * NH];
    __shared__ __align__(16) float qsh[VPB * NH];
    __shared__ float wmaxa[16], wmaxb[16];
    __shared__ __align__(16) float Ms[NV];
    __shared__ int idsh[16 * NT];

    const int tid = threadIdx.x;
    const int lane = tid & 31;
    const int warp = tid >> 5;
    const int v0i = blockIdx.x * VPB;
    const int b0 = blockIdx.x * BPB;
    const int h4 = lane * 4;

    // ============ prefetch EVERYTHING (one MLP window) ============
    const float ea0 = __ldg(emb + v0i * NE + lane);
    const float ea1 = __ldg(emb + v0i * NE + 32 + lane);
    const float eb0 = __ldg(emb + (v0i + 1) * NE + lane);
    const float eb1 = __ldg(emb + (v0i + 1) * NE + 32 + lane);
    float wi0[8], wi1[8];
    float4 wv[8];
#pragma unroll
    for (int r = 0; r < 8; r++) {
        const int h = warp * 8 + r;
        wi0[r] = __ldg(W_in + h * NE + lane);
        wi1[r] = __ldg(W_in + h * NE + 32 + lane);
        wv[r] = __ldg((const float4*)(W_lif + h * NH + h4));
    }
    const float bin = (lane < 8) ? __ldg(b_in + warp * 8 + lane) : 0.f;
    const float bl0 = (lane < 8) ? __ldg(b_lif + warp * 8 + lane) : 0.f;
    float b1[4];
#pragma unroll
    for (int j = 0; j < 4; j++) b1[j] = __ldg(b_lif + NH + h4 + j);
    const float bc = (lane < NC) ? __ldg(b_cls + lane) : 0.f;
    // bias_safe computed pre-barrier (off the post-barrier chain)
    const bool bias_safe = __all_sync(
        FULL, (0.2f * b1[0] < 0.19999f) && (0.2f * b1[1] < 0.19999f) &&
                  (0.2f * b1[2] < 0.19999f) && (0.2f * b1[3] < 0.19999f));

    // ============ prep: P[v,h] = emb[v]@W_in[h,:] + b_in[h] ============
    {
        float pa[8], pb[8];
#pragma unroll
        for (int r = 0; r < 8; r++) {
            pa[r] = fmaf(wi0[r], ea0, wi1[r] * ea1);
            pb[r] = fmaf(wi0[r], eb0, wi1[r] * eb1);
        }
#pragma unroll
        for (int r = 0; r < 8; r++) {
#pragma unroll
            for (int d = 16; d > 0; d >>= 1) {
                pa[r] += __shfl_xor_sync(FULL, pa[r], d);
                pb[r] += __shfl_xor_sync(FULL, pb[r], d);
            }
            if (lane == r) {
                psh[warp * 8 + r] = pa[r] + bin;
                psh[NH + warp * 8 + r] = pb[r] + bin;
            }
        }
    }
    __syncthreads();

    // ============ prep: Q[v,h] = 0.2*(P[v] . W_lif0[h,:] + b_lif0[h]) =====
    {
        const float4 pva = *(const float4*)(psh + h4);
        const float4 pvb = *(const float4*)(psh + NH + h4);
        float qa[8], qb[8];
#pragma unroll
        for (int r = 0; r < 8; r++) {
            qa[r] = fmaf(wv[r].x, pva.x,
                         fmaf(wv[r].y, pva.y,
                              fmaf(wv[r].z, pva.z, wv[r].w * pva.w)));
            qb[r] = fmaf(wv[r].x, pvb.x,
                         fmaf(wv[r].y, pvb.y,
                              fmaf(wv[r].z, pvb.z, wv[r].w * pvb.w)));
        }
        float qav = -1e30f, qbv = -1e30f;
#pragma unroll
        for (int r = 0; r < 8; r++) {
#pragma unroll
            for (int d = 16; d > 0; d >>= 1) {
                qa[r] += __shfl_xor_sync(FULL, qa[r], d);
                qb[r] += __shfl_xor_sync(FULL, qb[r], d);
            }
            if (lane == r) {
                const float qqa = 0.2f * (qa[r] + bl0);
                const float qqb = 0.2f * (qb[r] + bl0);
                qsh[warp * 8 + r] = qqa;
                qsh[NH + warp * 8 + r] = qqb;
                qav = qqa;
                qbv = qqb;
            }
        }
#pragma unroll
        for (int d = 16; d > 0; d >>= 1) {
            qav = fmaxf(qav, __shfl_xor_sync(FULL, qav, d));
            qbv = fmaxf(qbv, __shfl_xor_sync(FULL, qbv, d));
        }
        if (lane == 0) {
            wmaxa[warp] = qav;
            wmaxb[warp] = qbv;
        }
    }
    __syncthreads();

    // ============ certificate contribution + barrier ============
    if (tid == 0) {
        float ma = wmaxa[0], mb = wmaxb[0];
#pragma unroll
        for (int w = 1; w < 16; w++) {
            ma = fmaxf(ma, wmaxa[w]);
            mb = fmaxf(mb, wmaxb[w]);
        }
        // clamped-at-0, order-encoded (nonneg floats preserve order in uint
        // once MSB set). Idempotent across graph replays.
        const float g = fmaxf(fmaxf(ma, mb), 0.f);
        atomicMax(&g_gmax, __float_as_uint(g) | 0x80000000u);
    }
    epoch_barrier(&g_cnt1, tid);  // tid0 fence orders its atomicMax too

    // ============ tier 0: global no-spike certificate ============
    // u_t <= sum_j 0.8^j max_v M[v] <= 5*max(M*,0) for every batch/step.
    const float gmax = __uint_as_float(ld_cg(&g_gmax) & 0x7FFFFFFFu);

    if (bias_safe && 5.0f * gmax < THRESH) {
        // no layer-0 spike possible anywhere -> acc == 0 -> logits = b_cls
        if (lane < NC) {
            out[(b0 + warp) * NC + lane] = bc;
            out[(b0 + 16 + warp) * NC + lane] = bc;
        }
        return;  // globally uniform decision
    }

    // ============ tier 1+: publish g_M/g_Q, then scan/replay (exact) ======
    if (tid == 0) {
        float ma = wmaxa[0], mb = wmaxb[0];
#pragma unroll
        for (int w = 1; w < 16; w++) {
            ma = fmaxf(ma, wmaxa[w]);
            mb = fmaxf(mb, wmaxb[w]);
        }
        g_M[v0i] = ma;
        g_M[v0i + 1] = mb;
    }
    if (tid < VPB * NH) g_Q[v0i * NH + tid] = qsh[tid];
    __syncthreads();
    epoch_barrier(&g_cnt2, tid);  // all blocks' g_M/g_Q visible past here

    if (tid < NV / 4) ((float4*)Ms)[tid] = ((const float4*)g_M)[tid];
    __syncthreads();

    const float* W1 = W_lif + NH * NH;

    for (int bb = 0; bb < 2; bb++) {
        const int b = b0 + bb * 16 + warp;
        int myid[8];
#pragma unroll
        for (int c = 0; c < 8; c++)
            myid[c] = __ldg(ids + b * NT + c * 32 + lane);

        // phase 1: carry-independent chunk scans
        float mxs[8], s31[8];
#pragma unroll
        for (int c = 0; c < 8; c++) {
            float s = Ms[myid[c]];
            float o;
            o = __shfl_up_sync(FULL, s, 1);
            if (lane >= 1) s = fmaf(P8_1, o, s);
            o = __shfl_up_sync(FULL, s, 2);
            if (lane >= 2) s = fmaf(P8_2, o, s);
            o = __shfl_up_sync(FULL, s, 4);
            if (lane >= 4) s = fmaf(P8_4, o, s);
            o = __shfl_up_sync(FULL, s, 8);
            if (lane >= 8) s = fmaf(P8_8, o, s);
            o = __shfl_up_sync(FULL, s, 16);
            if (lane >= 16) s = fmaf(P8_16, o, s);
            float m = s;
#pragma unroll
            for (int d = 16; d > 0; d >>= 1)
                m = fmaxf(m, __shfl_xor_sync(FULL, m, d));
            mxs[c] = m;
            s31[c] = __shfl_sync(FULL, s, 31);
        }

        // phase 2: serial carry + (rare) exact replay
        float v0[4] = {0.f, 0.f, 0.f, 0.f};
        float v1[4] = {0.f, 0.f, 0.f, 0.f};
        float acc[4] = {0.f, 0.f, 0.f, 0.f};
        int tck = 0;
        float u = 0.f;
        bool staged = false;

        for (int c = 0; c < 8; c++) {
            const float bnd = fmaf(0.8f, fmaxf(u, 0.f), mxs[c]);
            if (!bias_safe || bnd >= THRESH) {
                if (!staged) {
#pragma unroll
                    for (int cc = 0; cc < 8; cc++)
                        idsh[warp * NT + cc * 32 + lane] = myid[cc];
                    __syncwarp();
                    staged = true;
                }
                const int tend = (c + 1) * 32;
                for (int t = tck; t < tend; t++) {
                    const int id = idsh[warp * NT + t];
                    const float4 q =
                        __ldg((const float4*)(g_Q + id * NH + h4));
                    float n0 = fmaf(0.8f, v0[0], q.x);
                    float n1 = fmaf(0.8f, v0[1], q.y);
                    float n2 = fmaf(0.8f, v0[2], q.z);
                    float n3 = fmaf(0.8f, v0[3], q.w);
                    unsigned bm[4];
                    bm[0] = __ballot_sync(FULL, n0 >= 1.0f);
                    bm[1] = __ballot_sync(FULL, n1 >= 1.0f);
                    bm[2] = __ballot_sync(FULL, n2 >= 1.0f);
                    bm[3] = __ballot_sync(FULL, n3 >= 1.0f);
                    v0[0] = (n0 >= 1.0f) ? 0.f : n0;
                    v0[1] = (n1 >= 1.0f) ? 0.f : n1;
                    v0[2] = (n2 >= 1.0f) ? 0.f : n2;
                    v0[3] = (n3 >= 1.0f) ? 0.f : n3;

                    float cur[4] = {0.f, 0.f, 0.f, 0.f};
#pragma unroll
                    for (int w = 0; w < 4; w++) {
                        unsigned mm = bm[w];
                        while (mm) {
                            const int l = __ffs(mm) - 1;
                            mm &= mm - 1;
                            const float* col = W1 + (l * 4 + w);
                            cur[0] += __ldg(col + (h4 + 0) * NH);
                            cur[1] += __ldg(col + (h4 + 1) * NH);
                            cur[2] += __ldg(col + (h4 + 2) * NH);
                            cur[3] += __ldg(col + (h4 + 3) * NH);
                        }
                    }
#pragma unroll
                    for (int j = 0; j < 4; j++) {
                        const float cc2 = cur[j] + b1[j];
                        const float vv = 0.8f * v1[j] + 0.2f * cc2;
                        const bool s = (vv >= 1.0f);
                        acc[j] += s ? 1.f : 0.f;
                        v1[j] = s ? 0.f : vv;
                    }
                }
                tck = tend;
                float w = fmaxf(fmaxf(v0[0], v0[1]), fmaxf(v0[2], v0[3]));
#pragma unroll
                for (int d = 16; d > 0; d >>= 1)
                    w = fmaxf(w, __shfl_xor_sync(FULL, w, d));
                u = w;
            } else {
                u = fmaf(P8_32, u, s31[c]);
            }
        }

        // epilogue for this batch
        if (tck == 0) {
            if (lane < NC) out[b * NC + lane] = bc;
        } else {
            const float invT = 1.0f / (float)NT;
#pragma unroll
            for (int cc = 0; cc < NC; cc++) {
                const float* wc = W_cls + cc * NH + h4;
                float p = acc[0] * __ldg(wc + 0) + acc[1] * __ldg(wc + 1) +
                          acc[2] * __ldg(wc + 2) + acc[3] * __ldg(wc + 3);
#pragma unroll
                for (int d = 16; d > 0; d >>= 1)
                    p += __shfl_xor_sync(FULL, p, d);
                if (lane == 0) out[b * NC + cc] = p * invT + b_cls[cc];
            }
        }
    }
}

// ---------------------------------------------------------------------------
// Host launcher (graph-capturable: ONE kernel launch)
// Input order: ids, emb, W_in, b_in, W_lif, b_lif, W_rec(unused), W_cls, b_cls
// ---------------------------------------------------------------------------
extern "C" void kernel_launch(void* const* d_in, const int* in_sizes, int n_in,
                              void* d_out, int out_size) {
    const int* ids = (const int*)d_in[0];
    const float* emb = (const float*)d_in[1];
    const float* W_in = (const float*)d_in[2];
    const float* b_in = (const float*)d_in[3];
    const float* W_lif = (const float*)d_in[4];
    const float* b_lif = (const float*)d_in[5];
    const float* W_cls = (const float*)d_in[7];
    const float* b_cls = (const float*)d_in[8];
    float* out = (float*)d_out;

    snn_fused_kernel<<<NBLK, NTHR>>>(ids, emb, W_in, b_in, W_lif, b_lif,
                                     W_cls, b_cls, out);
}